// round 13
// baseline (speedup 1.0000x reference)
#include <cuda_runtime.h>
#include <cuda_fp16.h>
#include <cstdint>

// ShiftConv: shift -> 1x1 conv (GEMM M=50176,N=512,K=512) -> BN -> ReLU.
// Round 13: CTA tile widened to 128p x 256o with 512 threads (16 warps,
// 4m x 4n of the SAME 32x64 warp tile / inner loop as R12). Halves A staging
// traffic + cp.async instruction count; 1 CTA/SM (full RF), 3-stage ring.

#define HDIM 28
#define HW   784
#define CCH  512
#define EPSV 1e-5f

#define MMA_F16(C, A, B) \
  asm volatile("mma.sync.aligned.m16n8k16.row.col.f32.f16.f16.f32 " \
    "{%0,%1,%2,%3}, {%4,%5,%6,%7}, {%8,%9}, {%0,%1,%2,%3};" \
    : "+f"((C)[0]), "+f"((C)[1]), "+f"((C)[2]), "+f"((C)[3]) \
    : "r"((A)[0]), "r"((A)[1]), "r"((A)[2]), "r"((A)[3]), \
      "r"((B)[0]), "r"((B)[1]))

#define LDSM4(R0, R1, R2, R3, addr) \
  asm volatile("ldmatrix.sync.aligned.m8n8.x4.shared.b16 {%0,%1,%2,%3}, [%4];" \
    : "=r"(R0), "=r"(R1), "=r"(R2), "=r"(R3) : "r"(addr))

#define CP16(dst, src) \
  asm volatile("cp.async.cg.shared.global [%0], [%1], 16;" :: "r"(dst), "l"(src))
#define CPCOMMIT() asm volatile("cp.async.commit_group;" ::: "memory")
#define CPWAIT(n)  asm volatile("cp.async.wait_group %0;" :: "n"(n) : "memory")

// K-chunk 64; smem row stride 64 real + 8 pad fp16 (144B, 16B aligned)
#define KC  64
#define KST 72
#define NSTAGE 3
#define A_BYTES (128 * KST * 2)            // 18432
#define B_BYTES (256 * KST * 2)            // 36864
#define A_OFF 0
#define B_OFF A_BYTES
#define STAGE_BYTES (A_BYTES + B_BYTES)    // 55296
#define SMEM_TOTAL (NSTAGE * STAGE_BYTES)  // 165888

__device__ __half g_Wh[CCH * CCH];
__device__ __half g_Ah[(size_t)50176 * CCH];   // shifted x, fp16, [p][c]

__device__ __forceinline__ uint32_t smem_u32(const void* p) {
    uint32_t a;
    asm("{ .reg .u64 t; cvta.to.shared.u64 t, %1; cvt.u32.u64 %0, t; }"
        : "=r"(a) : "l"(p));
    return a;
}

// Merged prepass. Blocks [0,1024): W fp32->fp16 convert.
// Blocks [1024, 1024+784*8): shift-gather + transpose + fp16 convert of x.
__global__ __launch_bounds__(256)
void prepass_kernel(const float* __restrict__ x, const float* __restrict__ Wm) {
    __shared__ float tile[64][65];
    __shared__ int soff[64];
    const int tid = threadIdx.x;
    const int bid = blockIdx.x;

    if (bid < 1024) {
        int i = bid * 256 + tid;
        g_Wh[i] = __float2half_rn(Wm[i]);
        return;
    }

    const int b2 = bid - 1024;
    const int p0 = (b2 >> 3) * 64;
    const int c0 = (b2 & 7) * 64;
    const int g  = c0 >> 7;

    if (tid < 64) {
        int pg = p0 + tid;
        int b  = pg / HW;
        int hw = pg - b * HW;
        int h  = hw / HDIM;
        int w  = hw - h * HDIM;
        int hs = h, ws = w;
        if      (g == 0) hs = (h + 1) % HDIM;
        else if (g == 1) hs = (h + HDIM - 1) % HDIM;
        else if (g == 2) ws = (w + 1) % HDIM;
        else             ws = (w + HDIM - 1) % HDIM;
        soff[tid] = b * (CCH * HW) + hs * HDIM + ws;
    }
    __syncthreads();
    #pragma unroll
    for (int it = 0; it < 16; it++) {       // read coalesced over p
        int lin = tid + it * 256;
        int c = lin >> 6, p = lin & 63;
        tile[c][p] = x[(size_t)(c0 + c) * HW + soff[p]];
    }
    __syncthreads();
    // write phase: 2 channels per thread, uint32 (half2) stores, coalesced
    #pragma unroll
    for (int it = 0; it < 8; it++) {
        int lin = tid + it * 256;           // 0..2047
        int p  = lin >> 5;                  // 0..63
        int cp = lin & 31;                  // channel pair 0..31
        int c  = cp * 2;
        __half h0 = __float2half_rn(tile[c][p]);
        __half h1 = __float2half_rn(tile[c + 1][p]);
        uint32_t pk = ((uint32_t)__half_as_ushort(h1) << 16) | __half_as_ushort(h0);
        *(uint32_t*)&g_Ah[(size_t)(p0 + p) * CCH + c0 + c] = pk;
    }
}

__global__ __launch_bounds__(512, 1)
void shiftconv_gemm(const float* __restrict__ gamma,
                    const float* __restrict__ beta,
                    const float* __restrict__ rmean,
                    const float* __restrict__ rvar,
                    float* __restrict__ out)
{
    extern __shared__ char dsm[];
    __shared__ float ssc[256], ssh[256];

    const int tid  = threadIdx.x;
    const int lane = tid & 31;
    const int wid  = tid >> 5;         // 0..15
    const int wm   = wid & 3;          // 4 m-warps x 32 rows
    const int wn   = wid >> 2;         // 4 n-warps x 64 cols
    const int g8   = lane >> 2;
    const int tig2 = (lane & 3) * 2;
    const int q    = lane >> 3;        // ldmatrix quad
    const int r8   = lane & 7;         // ldmatrix row within matrix

    const int pblock = blockIdx.x * 128;
    const int oblock = blockIdx.y * 256;

    if (tid < 256) {
        int o = oblock + tid;
        float sc = gamma[o] * rsqrtf(rvar[o] + EPSV);
        ssc[tid] = sc;
        ssh[tid] = beta[o] - rmean[o] * sc;
    }

    const uint32_t sdyn = smem_u32(dsm);

    uint32_t aoff[2];
    #pragma unroll
    for (int mt = 0; mt < 2; mt++)
        aoff[mt] = (uint32_t)(((wm * 32 + mt * 16 + (q & 1) * 8 + r8) * KST
                               + (q >> 1) * 8) * 2) + A_OFF;
    uint32_t boff[4];
    #pragma unroll
    for (int np = 0; np < 4; np++)
        boff[np] = (uint32_t)(((wn * 64 + np * 16 + (q >> 1) * 8 + r8) * KST
                               + (q & 1) * 8) * 2) + B_OFF;

    // stage loader: A 128 rows + B 256 rows x 128B; 6 x 16B cp.async/thread
    auto load_stage = [&](int ch) {
        int kc = ch * KC;
        uint32_t st = sdyn + (ch % NSTAGE) * STAGE_BYTES;
        #pragma unroll
        for (int it = 0; it < 2; it++) {    // A: 1024 chunks
            int lin = tid + it * 512;
            int r = lin >> 3;
            int j = lin & 7;
            CP16(st + A_OFF + r * (KST * 2) + j * 16,
                 &g_Ah[(size_t)(pblock + r) * CCH + kc + j * 8]);
        }
        #pragma unroll
        for (int it = 0; it < 4; it++) {    // B: 2048 chunks
            int lin = tid + it * 512;
            int r = lin >> 3;
            int j = lin & 7;
            CP16(st + B_OFF + r * (KST * 2) + j * 16,
                 &g_Wh[(size_t)(oblock + r) * CCH + kc + j * 8]);
        }
        CPCOMMIT();
    };

    float acc[2][8][4];
    #pragma unroll
    for (int mt = 0; mt < 2; mt++)
        #pragma unroll
        for (int nt = 0; nt < 8; nt++)
            #pragma unroll
            for (int rr = 0; rr < 4; rr++) acc[mt][nt][rr] = 0.0f;

    load_stage(0);
    load_stage(1);

    #pragma unroll
    for (int ch = 0; ch < 8; ch++) {
        if (ch < 7) CPWAIT(1);
        else        CPWAIT(0);
        __syncthreads();   // compute(ch-1) fully done -> buffer (ch-1)%3 free

        if (ch < 6) load_stage(ch + 2);   // writes buffer (ch+2)%3 == (ch-1)%3

        const uint32_t st = sdyn + (ch % NSTAGE) * STAGE_BYTES;
        #pragma unroll
        for (int kk = 0; kk < KC; kk += 16) {
            const uint32_t kb = st + kk * 2;
            uint32_t ah[2][4];
            uint32_t bh[8][2];
            LDSM4(ah[0][0], ah[0][1], ah[0][2], ah[0][3], kb + aoff[0]);
            LDSM4(ah[1][0], ah[1][1], ah[1][2], ah[1][3], kb + aoff[1]);
            LDSM4(bh[0][0], bh[0][1], bh[1][0], bh[1][1], kb + boff[0]);
            LDSM4(bh[2][0], bh[2][1], bh[3][0], bh[3][1], kb + boff[1]);

            MMA_F16(acc[0][0], ah[0], bh[0]);
            MMA_F16(acc[1][0], ah[1], bh[0]);
            MMA_F16(acc[0][1], ah[0], bh[1]);
            MMA_F16(acc[1][1], ah[1], bh[1]);
            LDSM4(bh[4][0], bh[4][1], bh[5][0], bh[5][1], kb + boff[2]);
            MMA_F16(acc[0][2], ah[0], bh[2]);
            MMA_F16(acc[1][2], ah[1], bh[2]);
            MMA_F16(acc[0][3], ah[0], bh[3]);
            MMA_F16(acc[1][3], ah[1], bh[3]);
            LDSM4(bh[6][0], bh[6][1], bh[7][0], bh[7][1], kb + boff[3]);
            MMA_F16(acc[0][4], ah[0], bh[4]);
            MMA_F16(acc[1][4], ah[1], bh[4]);
            MMA_F16(acc[0][5], ah[0], bh[5]);
            MMA_F16(acc[1][5], ah[1], bh[5]);
            MMA_F16(acc[0][6], ah[0], bh[6]);
            MMA_F16(acc[1][6], ah[1], bh[6]);
            MMA_F16(acc[0][7], ah[0], bh[7]);
            MMA_F16(acc[1][7], ah[1], bh[7]);
        }
    }

    // Epilogue: BN + ReLU.
    #pragma unroll
    for (int mt = 0; mt < 2; mt++) {
        int p0 = pblock + wm * 32 + mt * 16 + g8;
        int p1 = p0 + 8;
        int b0 = p0 / HW, hw0 = p0 - b0 * HW;
        int b1 = p1 / HW, hw1 = p1 - b1 * HW;
        #pragma unroll
        for (int nt = 0; nt < 8; nt++) {
            int oo  = wn * 64 + nt * 8 + tig2;
            float sc0 = ssc[oo],     sh0 = ssh[oo];
            float sc1 = ssc[oo + 1], sh1 = ssh[oo + 1];
            int o0 = oblock + oo;
            float* q00 = out + ((size_t)(b0 * CCH + o0)) * HW + hw0;
            float* q01 = out + ((size_t)(b0 * CCH + o0 + 1)) * HW + hw0;
            float* q10 = out + ((size_t)(b1 * CCH + o0)) * HW + hw1;
            float* q11 = out + ((size_t)(b1 * CCH + o0 + 1)) * HW + hw1;
            *q00 = fmaxf(fmaf(acc[mt][nt][0], sc0, sh0), 0.0f);
            *q01 = fmaxf(fmaf(acc[mt][nt][1], sc1, sh1), 0.0f);
            *q10 = fmaxf(fmaf(acc[mt][nt][2], sc0, sh0), 0.0f);
            *q11 = fmaxf(fmaf(acc[mt][nt][3], sc1, sh1), 0.0f);
        }
    }
}

extern "C" void kernel_launch(void* const* d_in, const int* in_sizes, int n_in,
                              void* d_out, int out_size)
{
    const float* x     = (const float*)d_in[0];
    const float* Wm    = (const float*)d_in[1];
    const float* gamma = (const float*)d_in[2];
    const float* beta  = (const float*)d_in[3];
    const float* rmean = (const float*)d_in[4];
    const float* rvar  = (const float*)d_in[5];
    float* out = (float*)d_out;

    cudaFuncSetAttribute(shiftconv_gemm,
                         cudaFuncAttributeMaxDynamicSharedMemorySize, SMEM_TOTAL);

    prepass_kernel<<<1024 + 784 * 8, 256>>>(x, Wm);
    dim3 grid(392, 2);   // 128p x 256o tiles
    shiftconv_gemm<<<grid, 512, SMEM_TOTAL>>>(gamma, beta, rmean, rvar, out);
}

// round 14
// speedup vs baseline: 1.0984x; 1.0984x over previous
#include <cuda_runtime.h>
#include <cuda_fp16.h>
#include <cstdint>

// ShiftConv: shift -> 1x1 conv (GEMM M=50176,N=512,K=512) -> BN -> ReLU.
// Round 14: warp tile enlarged to 64x64 (4 warps of 128 threads, CTA tile
// still 128x128, 2 CTAs/SM preserved). LDSM traffic per MMA drops 192B->128B,
// flipping the binding pipe from smem crossbar to tensor. Ring/prepass = R12.

#define HDIM 28
#define HW   784
#define CCH  512
#define EPSV 1e-5f

#define MMA_F16(C, A, B) \
  asm volatile("mma.sync.aligned.m16n8k16.row.col.f32.f16.f16.f32 " \
    "{%0,%1,%2,%3}, {%4,%5,%6,%7}, {%8,%9}, {%0,%1,%2,%3};" \
    : "+f"((C)[0]), "+f"((C)[1]), "+f"((C)[2]), "+f"((C)[3]) \
    : "r"((A)[0]), "r"((A)[1]), "r"((A)[2]), "r"((A)[3]), \
      "r"((B)[0]), "r"((B)[1]))

#define LDSM4(R0, R1, R2, R3, addr) \
  asm volatile("ldmatrix.sync.aligned.m8n8.x4.shared.b16 {%0,%1,%2,%3}, [%4];" \
    : "=r"(R0), "=r"(R1), "=r"(R2), "=r"(R3) : "r"(addr))

#define CP16(dst, src) \
  asm volatile("cp.async.cg.shared.global [%0], [%1], 16;" :: "r"(dst), "l"(src))
#define CPCOMMIT() asm volatile("cp.async.commit_group;" ::: "memory")
#define CPWAIT(n)  asm volatile("cp.async.wait_group %0;" :: "n"(n) : "memory")

// K-chunk 64; smem row stride 64 real + 8 pad fp16 (144B, 16B aligned)
#define KC  64
#define KST 72
#define NSTAGE 3
#define MAT_BYTES (128 * KST * 2)          // 18432
#define A_OFF 0
#define B_OFF MAT_BYTES
#define STAGE_BYTES (2 * MAT_BYTES)        // 36864
#define SMEM_TOTAL (NSTAGE * STAGE_BYTES)  // 110592

__device__ __half g_Wh[CCH * CCH];
__device__ __half g_Ah[(size_t)50176 * CCH];   // shifted x, fp16, [p][c]

__device__ __forceinline__ uint32_t smem_u32(const void* p) {
    uint32_t a;
    asm("{ .reg .u64 t; cvta.to.shared.u64 t, %1; cvt.u32.u64 %0, t; }"
        : "=r"(a) : "l"(p));
    return a;
}

// Merged prepass. Blocks [0,1024): W fp32->fp16 convert.
// Blocks [1024, 1024+784*8): shift-gather + transpose + fp16 convert of x.
__global__ __launch_bounds__(256)
void prepass_kernel(const float* __restrict__ x, const float* __restrict__ Wm) {
    __shared__ float tile[64][65];
    __shared__ int soff[64];
    const int tid = threadIdx.x;
    const int bid = blockIdx.x;

    if (bid < 1024) {
        int i = bid * 256 + tid;
        g_Wh[i] = __float2half_rn(Wm[i]);
        return;
    }

    const int b2 = bid - 1024;
    const int p0 = (b2 >> 3) * 64;
    const int c0 = (b2 & 7) * 64;
    const int g  = c0 >> 7;

    if (tid < 64) {
        int pg = p0 + tid;
        int b  = pg / HW;
        int hw = pg - b * HW;
        int h  = hw / HDIM;
        int w  = hw - h * HDIM;
        int hs = h, ws = w;
        if      (g == 0) hs = (h + 1) % HDIM;
        else if (g == 1) hs = (h + HDIM - 1) % HDIM;
        else if (g == 2) ws = (w + 1) % HDIM;
        else             ws = (w + HDIM - 1) % HDIM;
        soff[tid] = b * (CCH * HW) + hs * HDIM + ws;
    }
    __syncthreads();
    #pragma unroll
    for (int it = 0; it < 16; it++) {       // read coalesced over p
        int lin = tid + it * 256;
        int c = lin >> 6, p = lin & 63;
        tile[c][p] = x[(size_t)(c0 + c) * HW + soff[p]];
    }
    __syncthreads();
    // write phase: 2 channels per thread, uint32 (half2) stores, coalesced
    #pragma unroll
    for (int it = 0; it < 8; it++) {
        int lin = tid + it * 256;           // 0..2047
        int p  = lin >> 5;                  // 0..63
        int cp = lin & 31;                  // channel pair 0..31
        int c  = cp * 2;
        __half h0 = __float2half_rn(tile[c][p]);
        __half h1 = __float2half_rn(tile[c + 1][p]);
        uint32_t pk = ((uint32_t)__half_as_ushort(h1) << 16) | __half_as_ushort(h0);
        *(uint32_t*)&g_Ah[(size_t)(p0 + p) * CCH + c0 + c] = pk;
    }
}

__global__ __launch_bounds__(128, 2)
void shiftconv_gemm(const float* __restrict__ gamma,
                    const float* __restrict__ beta,
                    const float* __restrict__ rmean,
                    const float* __restrict__ rvar,
                    float* __restrict__ out)
{
    extern __shared__ char dsm[];
    __shared__ float ssc[128], ssh[128];

    const int tid  = threadIdx.x;
    const int lane = tid & 31;
    const int wid  = tid >> 5;         // 0..3
    const int wm   = wid & 1;          // 2 m-warps x 64 rows
    const int wn   = wid >> 1;         // 2 n-warps x 64 cols
    const int g8   = lane >> 2;
    const int tig2 = (lane & 3) * 2;
    const int q    = lane >> 3;        // ldmatrix quad
    const int r8   = lane & 7;         // ldmatrix row within matrix

    const int pblock = blockIdx.x * 128;
    const int oblock = blockIdx.y * 128;

    if (tid < 128) {
        int o = oblock + tid;
        float sc = gamma[o] * rsqrtf(rvar[o] + EPSV);
        ssc[tid] = sc;
        ssh[tid] = beta[o] - rmean[o] * sc;
    }

    const uint32_t sdyn = smem_u32(dsm);

    // A: 4 m16-tiles per warp (64 rows)
    uint32_t aoff[4];
    #pragma unroll
    for (int mt = 0; mt < 4; mt++)
        aoff[mt] = (uint32_t)(((wm * 64 + mt * 16 + (q & 1) * 8 + r8) * KST
                               + (q >> 1) * 8) * 2) + A_OFF;
    // B: 4 n16-pairs per warp (64 cols, each LDSM4 covers 2 n8-tiles)
    uint32_t boff[4];
    #pragma unroll
    for (int np = 0; np < 4; np++)
        boff[np] = (uint32_t)(((wn * 64 + np * 16 + (q >> 1) * 8 + r8) * KST
                               + (q & 1) * 8) * 2) + B_OFF;

    // stage loader: A+B 256 rows x 128B = 2048 x 16B chunks, 16 per thread
    auto load_stage = [&](int ch) {
        int kc = ch * KC;
        uint32_t st = sdyn + (ch % NSTAGE) * STAGE_BYTES;
        #pragma unroll
        for (int it = 0; it < 8; it++) {
            int lin = tid + it * 128;
            int r = lin >> 3;
            int j = lin & 7;
            uint32_t d = st + r * (KST * 2) + j * 16;
            CP16(d + A_OFF, &g_Ah[(size_t)(pblock + r) * CCH + kc + j * 8]);
            CP16(d + B_OFF, &g_Wh[(size_t)(oblock + r) * CCH + kc + j * 8]);
        }
        CPCOMMIT();
    };

    float acc[4][8][4];
    #pragma unroll
    for (int mt = 0; mt < 4; mt++)
        #pragma unroll
        for (int nt = 0; nt < 8; nt++)
            #pragma unroll
            for (int rr = 0; rr < 4; rr++) acc[mt][nt][rr] = 0.0f;

    load_stage(0);
    load_stage(1);

    #pragma unroll
    for (int ch = 0; ch < 8; ch++) {
        if (ch < 7) CPWAIT(1);
        else        CPWAIT(0);
        __syncthreads();   // compute(ch-1) fully done -> buffer (ch-1)%3 free

        if (ch < 6) load_stage(ch + 2);   // writes buffer (ch+2)%3 == (ch-1)%3

        const uint32_t st = sdyn + (ch % NSTAGE) * STAGE_BYTES;
        #pragma unroll
        for (int kk = 0; kk < KC; kk += 16) {
            const uint32_t kb = st + kk * 2;
            uint32_t ah[4][4];
            uint32_t bh[8][2];
            LDSM4(ah[0][0], ah[0][1], ah[0][2], ah[0][3], kb + aoff[0]);
            LDSM4(ah[1][0], ah[1][1], ah[1][2], ah[1][3], kb + aoff[1]);
            LDSM4(ah[2][0], ah[2][1], ah[2][2], ah[2][3], kb + aoff[2]);
            LDSM4(ah[3][0], ah[3][1], ah[3][2], ah[3][3], kb + aoff[3]);
            LDSM4(bh[0][0], bh[0][1], bh[1][0], bh[1][1], kb + boff[0]);
            LDSM4(bh[2][0], bh[2][1], bh[3][0], bh[3][1], kb + boff[1]);

            #pragma unroll
            for (int mt = 0; mt < 4; mt++) {
                MMA_F16(acc[mt][0], ah[mt], bh[0]);
                MMA_F16(acc[mt][1], ah[mt], bh[1]);
            }
            LDSM4(bh[4][0], bh[4][1], bh[5][0], bh[5][1], kb + boff[2]);
            #pragma unroll
            for (int mt = 0; mt < 4; mt++) {
                MMA_F16(acc[mt][2], ah[mt], bh[2]);
                MMA_F16(acc[mt][3], ah[mt], bh[3]);
            }
            LDSM4(bh[6][0], bh[6][1], bh[7][0], bh[7][1], kb + boff[3]);
            #pragma unroll
            for (int mt = 0; mt < 4; mt++) {
                MMA_F16(acc[mt][4], ah[mt], bh[4]);
                MMA_F16(acc[mt][5], ah[mt], bh[5]);
            }
            #pragma unroll
            for (int mt = 0; mt < 4; mt++) {
                MMA_F16(acc[mt][6], ah[mt], bh[6]);
                MMA_F16(acc[mt][7], ah[mt], bh[7]);
            }
        }
    }

    // Epilogue: BN + ReLU.
    #pragma unroll
    for (int mt = 0; mt < 4; mt++) {
        int p0 = pblock + wm * 64 + mt * 16 + g8;
        int p1 = p0 + 8;
        int b0 = p0 / HW, hw0 = p0 - b0 * HW;
        int b1 = p1 / HW, hw1 = p1 - b1 * HW;
        #pragma unroll
        for (int nt = 0; nt < 8; nt++) {
            int oo  = wn * 64 + nt * 8 + tig2;
            float sc0 = ssc[oo],     sh0 = ssh[oo];
            float sc1 = ssc[oo + 1], sh1 = ssh[oo + 1];
            int o0 = oblock + oo;
            float* q00 = out + ((size_t)(b0 * CCH + o0)) * HW + hw0;
            float* q01 = out + ((size_t)(b0 * CCH + o0 + 1)) * HW + hw0;
            float* q10 = out + ((size_t)(b1 * CCH + o0)) * HW + hw1;
            float* q11 = out + ((size_t)(b1 * CCH + o0 + 1)) * HW + hw1;
            *q00 = fmaxf(fmaf(acc[mt][nt][0], sc0, sh0), 0.0f);
            *q01 = fmaxf(fmaf(acc[mt][nt][1], sc1, sh1), 0.0f);
            *q10 = fmaxf(fmaf(acc[mt][nt][2], sc0, sh0), 0.0f);
            *q11 = fmaxf(fmaf(acc[mt][nt][3], sc1, sh1), 0.0f);
        }
    }
}

extern "C" void kernel_launch(void* const* d_in, const int* in_sizes, int n_in,
                              void* d_out, int out_size)
{
    const float* x     = (const float*)d_in[0];
    const float* Wm    = (const float*)d_in[1];
    const float* gamma = (const float*)d_in[2];
    const float* beta  = (const float*)d_in[3];
    const float* rmean = (const float*)d_in[4];
    const float* rvar  = (const float*)d_in[5];
    float* out = (float*)d_out;

    cudaFuncSetAttribute(shiftconv_gemm,
                         cudaFuncAttributeMaxDynamicSharedMemorySize, SMEM_TOTAL);

    prepass_kernel<<<1024 + 784 * 8, 256>>>(x, Wm);
    dim3 grid(392, 4);
    shiftconv_gemm<<<grid, 128, SMEM_TOTAL>>>(gamma, beta, rmean, rvar, out);
}

// round 15
// speedup vs baseline: 1.1242x; 1.0234x over previous
#include <cuda_runtime.h>
#include <cuda_fp16.h>
#include <cstdint>

// ShiftConv: shift -> 1x1 conv (GEMM M=50176,N=512,K=512) -> BN -> ReLU.
// Round 15: GEMM byte-identical to R12 (83.3us, at the mma.sync structural
// ceiling ~52% tensor; tcgen05 blocked by harness sm_103 target). Prepass
// write phase restructured: warp lanes cover 8 c-octets x 4 p, so each
// STG.128 warp-instr writes 4 fully-coalesced 128B lines; packing via
// cvt.f16x2 (8 ops vs ~28). Targets the 33us prepass share.

#define HDIM 28
#define HW   784
#define CCH  512
#define EPSV 1e-5f

#define MMA_F16(C, A, B) \
  asm volatile("mma.sync.aligned.m16n8k16.row.col.f32.f16.f16.f32 " \
    "{%0,%1,%2,%3}, {%4,%5,%6,%7}, {%8,%9}, {%0,%1,%2,%3};" \
    : "+f"((C)[0]), "+f"((C)[1]), "+f"((C)[2]), "+f"((C)[3]) \
    : "r"((A)[0]), "r"((A)[1]), "r"((A)[2]), "r"((A)[3]), \
      "r"((B)[0]), "r"((B)[1]))

#define LDSM4(R0, R1, R2, R3, addr) \
  asm volatile("ldmatrix.sync.aligned.m8n8.x4.shared.b16 {%0,%1,%2,%3}, [%4];" \
    : "=r"(R0), "=r"(R1), "=r"(R2), "=r"(R3) : "r"(addr))

#define CP16(dst, src) \
  asm volatile("cp.async.cg.shared.global [%0], [%1], 16;" :: "r"(dst), "l"(src))
#define CPCOMMIT() asm volatile("cp.async.commit_group;" ::: "memory")
#define CPWAIT(n)  asm volatile("cp.async.wait_group %0;" :: "n"(n) : "memory")

// K-chunk 64; smem row stride 64 real + 8 pad fp16 (144B, 16B aligned)
#define KC  64
#define KST 72
#define NSTAGE 3
#define MAT_BYTES (128 * KST * 2)          // 18432
#define A_OFF 0
#define B_OFF MAT_BYTES
#define STAGE_BYTES (2 * MAT_BYTES)        // 36864
#define SMEM_TOTAL (NSTAGE * STAGE_BYTES)  // 110592

__device__ __half g_Wh[CCH * CCH];
__device__ __half g_Ah[(size_t)50176 * CCH];   // shifted x, fp16, [p][c]

__device__ __forceinline__ uint32_t smem_u32(const void* p) {
    uint32_t a;
    asm("{ .reg .u64 t; cvta.to.shared.u64 t, %1; cvt.u32.u64 %0, t; }"
        : "=r"(a) : "l"(p));
    return a;
}

// Merged prepass. Blocks [0,1024): W fp32->fp16 convert.
// Blocks [1024, 1024+784*8): shift-gather + transpose + fp16 convert of x.
__global__ __launch_bounds__(256)
void prepass_kernel(const float* __restrict__ x, const float* __restrict__ Wm) {
    __shared__ float tile[64][65];
    __shared__ int soff[64];
    const int tid = threadIdx.x;
    const int bid = blockIdx.x;

    if (bid < 1024) {
        int i = bid * 256 + tid;
        g_Wh[i] = __float2half_rn(Wm[i]);
        return;
    }

    const int b2 = bid - 1024;
    const int p0 = (b2 >> 3) * 64;
    const int c0 = (b2 & 7) * 64;
    const int g  = c0 >> 7;

    if (tid < 64) {
        int pg = p0 + tid;
        int b  = pg / HW;
        int hw = pg - b * HW;
        int h  = hw / HDIM;
        int w  = hw - h * HDIM;
        int hs = h, ws = w;
        if      (g == 0) hs = (h + 1) % HDIM;
        else if (g == 1) hs = (h + HDIM - 1) % HDIM;
        else if (g == 2) ws = (w + 1) % HDIM;
        else             ws = (w + HDIM - 1) % HDIM;
        soff[tid] = b * (CCH * HW) + hs * HDIM + ws;
    }
    __syncthreads();
    #pragma unroll
    for (int it = 0; it < 16; it++) {       // read coalesced over p
        int lin = tid + it * 256;
        int c = lin >> 6, p = lin & 63;
        tile[c][p] = x[(size_t)(c0 + c) * HW + soff[p]];
    }
    __syncthreads();
    // write phase: each thread packs one 8-channel octet for one p and does a
    // single STG.128; warp lanes span 8 octets x 4 p -> 4 coalesced 128B lines
    // per warp store instead of 8 scattered STG.32 per thread.
    #pragma unroll
    for (int it = 0; it < 2; it++) {
        int lin = tid + it * 256;           // 0..511
        int oct = lin & 7;                  // c-octet within the 64-c tile
        int p   = lin >> 3;                 // 0..63
        int c   = oct * 8;
        uint32_t pk[4];
        #pragma unroll
        for (int j = 0; j < 4; j++) {
            __half2 h2 = __floats2half2_rn(tile[c + 2 * j][p],
                                           tile[c + 2 * j + 1][p]);
            pk[j] = *(uint32_t*)&h2;
        }
        *(uint4*)&g_Ah[(size_t)(p0 + p) * CCH + c0 + c] =
            make_uint4(pk[0], pk[1], pk[2], pk[3]);
    }
}

__global__ __launch_bounds__(256, 2)
void shiftconv_gemm(const float* __restrict__ gamma,
                    const float* __restrict__ beta,
                    const float* __restrict__ rmean,
                    const float* __restrict__ rvar,
                    float* __restrict__ out)
{
    extern __shared__ char dsm[];
    __shared__ float ssc[128], ssh[128];

    const int tid  = threadIdx.x;
    const int lane = tid & 31;
    const int wid  = tid >> 5;
    const int wm   = wid & 3;
    const int wn   = wid >> 2;
    const int g8   = lane >> 2;
    const int tig2 = (lane & 3) * 2;
    const int q    = lane >> 3;        // ldmatrix quad
    const int r8   = lane & 7;         // ldmatrix row within matrix

    const int pblock = blockIdx.x * 128;
    const int oblock = blockIdx.y * 128;

    if (tid < 128) {
        int o = oblock + tid;
        float sc = gamma[o] * rsqrtf(rvar[o] + EPSV);
        ssc[tid] = sc;
        ssh[tid] = beta[o] - rmean[o] * sc;
    }

    const uint32_t sdyn = smem_u32(dsm);

    uint32_t aoff[2];
    #pragma unroll
    for (int mt = 0; mt < 2; mt++)
        aoff[mt] = (uint32_t)(((wm * 32 + mt * 16 + (q & 1) * 8 + r8) * KST
                               + (q >> 1) * 8) * 2) + A_OFF;
    uint32_t boff[4];
    #pragma unroll
    for (int np = 0; np < 4; np++)
        boff[np] = (uint32_t)(((wn * 64 + np * 16 + (q >> 1) * 8 + r8) * KST
                               + (q & 1) * 8) * 2) + B_OFF;

    auto load_stage = [&](int ch) {
        int kc = ch * KC;
        uint32_t st = sdyn + (ch % NSTAGE) * STAGE_BYTES;
        #pragma unroll
        for (int it = 0; it < 4; it++) {
            int lin = tid + it * 256;
            int r = lin >> 3;
            int j = lin & 7;
            uint32_t d = st + r * (KST * 2) + j * 16;
            CP16(d + A_OFF, &g_Ah[(size_t)(pblock + r) * CCH + kc + j * 8]);
            CP16(d + B_OFF, &g_Wh[(size_t)(oblock + r) * CCH + kc + j * 8]);
        }
        CPCOMMIT();
    };

    float acc[2][8][4];
    #pragma unroll
    for (int mt = 0; mt < 2; mt++)
        #pragma unroll
        for (int nt = 0; nt < 8; nt++)
            #pragma unroll
            for (int rr = 0; rr < 4; rr++) acc[mt][nt][rr] = 0.0f;

    load_stage(0);
    load_stage(1);

    #pragma unroll
    for (int ch = 0; ch < 8; ch++) {
        if (ch < 7) CPWAIT(1);
        else        CPWAIT(0);
        __syncthreads();   // compute(ch-1) fully done -> buffer (ch-1)%3 free

        if (ch < 6) load_stage(ch + 2);   // writes buffer (ch+2)%3 == (ch-1)%3

        const uint32_t st = sdyn + (ch % NSTAGE) * STAGE_BYTES;
        #pragma unroll
        for (int kk = 0; kk < KC; kk += 16) {
            const uint32_t kb = st + kk * 2;
            uint32_t ah[2][4];
            uint32_t bh[8][2];
            LDSM4(ah[0][0], ah[0][1], ah[0][2], ah[0][3], kb + aoff[0]);
            LDSM4(ah[1][0], ah[1][1], ah[1][2], ah[1][3], kb + aoff[1]);
            LDSM4(bh[0][0], bh[0][1], bh[1][0], bh[1][1], kb + boff[0]);
            LDSM4(bh[2][0], bh[2][1], bh[3][0], bh[3][1], kb + boff[1]);

            MMA_F16(acc[0][0], ah[0], bh[0]);
            MMA_F16(acc[1][0], ah[1], bh[0]);
            MMA_F16(acc[0][1], ah[0], bh[1]);
            MMA_F16(acc[1][1], ah[1], bh[1]);
            LDSM4(bh[4][0], bh[4][1], bh[5][0], bh[5][1], kb + boff[2]);
            MMA_F16(acc[0][2], ah[0], bh[2]);
            MMA_F16(acc[1][2], ah[1], bh[2]);
            MMA_F16(acc[0][3], ah[0], bh[3]);
            MMA_F16(acc[1][3], ah[1], bh[3]);
            LDSM4(bh[6][0], bh[6][1], bh[7][0], bh[7][1], kb + boff[3]);
            MMA_F16(acc[0][4], ah[0], bh[4]);
            MMA_F16(acc[1][4], ah[1], bh[4]);
            MMA_F16(acc[0][5], ah[0], bh[5]);
            MMA_F16(acc[1][5], ah[1], bh[5]);
            MMA_F16(acc[0][6], ah[0], bh[6]);
            MMA_F16(acc[1][6], ah[1], bh[6]);
            MMA_F16(acc[0][7], ah[0], bh[7]);
            MMA_F16(acc[1][7], ah[1], bh[7]);
        }
    }

    // Epilogue: BN + ReLU.
    #pragma unroll
    for (int mt = 0; mt < 2; mt++) {
        int p0 = pblock + wm * 32 + mt * 16 + g8;
        int p1 = p0 + 8;
        int b0 = p0 / HW, hw0 = p0 - b0 * HW;
        int b1 = p1 / HW, hw1 = p1 - b1 * HW;
        #pragma unroll
        for (int nt = 0; nt < 8; nt++) {
            int oo  = wn * 64 + nt * 8 + tig2;
            float sc0 = ssc[oo],     sh0 = ssh[oo];
            float sc1 = ssc[oo + 1], sh1 = ssh[oo + 1];
            int o0 = oblock + oo;
            float* q00 = out + ((size_t)(b0 * CCH + o0)) * HW + hw0;
            float* q01 = out + ((size_t)(b0 * CCH + o0 + 1)) * HW + hw0;
            float* q10 = out + ((size_t)(b1 * CCH + o0)) * HW + hw1;
            float* q11 = out + ((size_t)(b1 * CCH + o0 + 1)) * HW + hw1;
            *q00 = fmaxf(fmaf(acc[mt][nt][0], sc0, sh0), 0.0f);
            *q01 = fmaxf(fmaf(acc[mt][nt][1], sc1, sh1), 0.0f);
            *q10 = fmaxf(fmaf(acc[mt][nt][2], sc0, sh0), 0.0f);
            *q11 = fmaxf(fmaf(acc[mt][nt][3], sc1, sh1), 0.0f);
        }
    }
}

extern "C" void kernel_launch(void* const* d_in, const int* in_sizes, int n_in,
                              void* d_out, int out_size)
{
    const float* x     = (const float*)d_in[0];
    const float* Wm    = (const float*)d_in[1];
    const float* gamma = (const float*)d_in[2];
    const float* beta  = (const float*)d_in[3];
    const float* rmean = (const float*)d_in[4];
    const float* rvar  = (const float*)d_in[5];
    float* out = (float*)d_out;

    cudaFuncSetAttribute(shiftconv_gemm,
                         cudaFuncAttributeMaxDynamicSharedMemorySize, SMEM_TOTAL);

    prepass_kernel<<<1024 + 784 * 8, 256>>>(x, Wm);
    dim3 grid(392, 4);
    shiftconv_gemm<<<grid, 256, SMEM_TOTAL>>>(gamma, beta, rmean, rvar, out);
}